// round 1
// baseline (speedup 1.0000x reference)
#include <cuda_runtime.h>
#include <cuda_bf16.h>
#include <math.h>

#define BATCH 8
#define SEQ 1024
#define DM 1024
#define NH 16
#define DH 64
#define RANK 128
#define NC 64
#define NQK 32
#define NV 32
#define KC 8
#define KQK 4
#define KV 6

// ---------------- scratch (device globals, allowed) ----------------
__device__ float g_logc[BATCH * SEQ * NC];
__device__ float g_logqk[BATCH * SEQ * NQK];
__device__ float g_logv[BATCH * SEQ * NV];
__device__ float g_acc[BATCH * 128];
__device__ int   g_idx[BATCH * 3 * 8];
__device__ float g_val[BATCH * 3 * 8];
__device__ float g_sc[BATCH * DM * RANK];      // [b][d][r]
__device__ float g_eqk[BATCH * RANK * DM];     // [b][r][d]
__device__ float g_ev[BATCH * RANK * DM];
__device__ float g_h[BATCH * SEQ * RANK];
__device__ float g_Q[BATCH * SEQ * DM];
__device__ float g_V[BATCH * SEQ * DM];
__device__ float g_att[BATCH * SEQ * DM];

// ---------------- GEMM 64x64 tile, BK=16, 4x4 micro ----------------
// C[M,N] = A[M,K] @ B  (TB=false: B[K,N] row-major; TB=true: B[N,K] row-major -> A@B^T)
template<bool TB>
__global__ void __launch_bounds__(256) gemm64(const float* __restrict__ A,
                                              const float* __restrict__ B,
                                              float* __restrict__ C,
                                              int M, int N, int K,
                                              long sA, long sB, long sC) {
    __shared__ float As[16][64];
    __shared__ float Bs[16][64];
    const float* Ab = A + (long)blockIdx.z * sA;
    const float* Bb = B + (long)blockIdx.z * sB;
    float* Cb = C + (long)blockIdx.z * sC;
    const int m0 = blockIdx.y * 64, n0 = blockIdx.x * 64;
    const int tid = threadIdx.x, tx = tid & 15, ty = tid >> 4;
    float acc[4][4] = {};
    for (int k0 = 0; k0 < K; k0 += 16) {
        {
            int r = tid >> 2, c = (tid & 3) * 4;
            float4 v = *(const float4*)(Ab + (long)(m0 + r) * K + k0 + c);
            As[c + 0][r] = v.x; As[c + 1][r] = v.y; As[c + 2][r] = v.z; As[c + 3][r] = v.w;
        }
        if (TB) {
            int r = tid >> 2, c = (tid & 3) * 4;
            float4 v = make_float4(0.f, 0.f, 0.f, 0.f);
            if (n0 + r < N) v = *(const float4*)(Bb + (long)(n0 + r) * K + k0 + c);
            Bs[c + 0][r] = v.x; Bs[c + 1][r] = v.y; Bs[c + 2][r] = v.z; Bs[c + 3][r] = v.w;
        } else {
            int r = tid >> 4, c = (tid & 15) * 4;
            float4 v = make_float4(0.f, 0.f, 0.f, 0.f);
            if (n0 + c < N) v = *(const float4*)(Bb + (long)(k0 + r) * N + n0 + c);
            *(float4*)&Bs[r][c] = v;
        }
        __syncthreads();
#pragma unroll
        for (int kk = 0; kk < 16; kk++) {
            float a[4], bb[4];
            *(float4*)a  = *(const float4*)&As[kk][ty * 4];
            *(float4*)bb = *(const float4*)&Bs[kk][tx * 4];
#pragma unroll
            for (int i = 0; i < 4; i++)
#pragma unroll
                for (int j = 0; j < 4; j++)
                    acc[i][j] += a[i] * bb[j];
        }
        __syncthreads();
    }
#pragma unroll
    for (int i = 0; i < 4; i++) {
        int m = m0 + ty * 4 + i;
#pragma unroll
        for (int j = 0; j < 4; j++) {
            int n = n0 + tx * 4 + j;
            if (n < N) Cb[(long)m * N + n] = acc[i][j];
        }
    }
}

// ---------------- GEMM 128x128 tile, BK=8, 8x8 micro ----------------
template<bool TB>
__global__ void __launch_bounds__(256) gemm128(const float* __restrict__ A,
                                               const float* __restrict__ B,
                                               float* __restrict__ C,
                                               int M, int N, int K,
                                               long sA, long sB, long sC) {
    __shared__ float As[8][128];
    __shared__ float Bs[8][128];
    const float* Ab = A + (long)blockIdx.z * sA;
    const float* Bb = B + (long)blockIdx.z * sB;
    float* Cb = C + (long)blockIdx.z * sC;
    const int m0 = blockIdx.y * 128, n0 = blockIdx.x * 128;
    const int tid = threadIdx.x, tx = tid & 15, ty = tid >> 4;
    float acc[8][8] = {};
    for (int k0 = 0; k0 < K; k0 += 8) {
        {
            int r = tid >> 1, c = (tid & 1) * 4;
            float4 v = *(const float4*)(Ab + (long)(m0 + r) * K + k0 + c);
            As[c + 0][r] = v.x; As[c + 1][r] = v.y; As[c + 2][r] = v.z; As[c + 3][r] = v.w;
        }
        if (TB) {
            int r = tid >> 1, c = (tid & 1) * 4;
            float4 v = make_float4(0.f, 0.f, 0.f, 0.f);
            if (n0 + r < N) v = *(const float4*)(Bb + (long)(n0 + r) * K + k0 + c);
            Bs[c + 0][r] = v.x; Bs[c + 1][r] = v.y; Bs[c + 2][r] = v.z; Bs[c + 3][r] = v.w;
        } else {
            int r = tid >> 5, c = (tid & 31) * 4;
            float4 v = make_float4(0.f, 0.f, 0.f, 0.f);
            if (n0 + c < N) v = *(const float4*)(Bb + (long)(k0 + r) * N + n0 + c);
            *(float4*)&Bs[r][c] = v;
        }
        __syncthreads();
#pragma unroll
        for (int kk = 0; kk < 8; kk++) {
            float a[8], bb[8];
            *(float4*)&a[0]  = *(const float4*)&As[kk][ty * 4];
            *(float4*)&a[4]  = *(const float4*)&As[kk][64 + ty * 4];
            *(float4*)&bb[0] = *(const float4*)&Bs[kk][tx * 4];
            *(float4*)&bb[4] = *(const float4*)&Bs[kk][64 + tx * 4];
#pragma unroll
            for (int i = 0; i < 8; i++)
#pragma unroll
                for (int j = 0; j < 8; j++)
                    acc[i][j] += a[i] * bb[j];
        }
        __syncthreads();
    }
#pragma unroll
    for (int i = 0; i < 8; i++) {
        int m = m0 + ((i < 4) ? (ty * 4 + i) : (64 + ty * 4 + i - 4));
#pragma unroll
        for (int j = 0; j < 8; j++) {
            int n = n0 + ((j < 4) ? (tx * 4 + j) : (64 + tx * 4 + j - 4));
            if (n < N) Cb[(long)m * N + n] = acc[i][j];
        }
    }
}

// ---- softmax each router row, multiply by importance, in place ----
__global__ void softmax_weight_kernel(float* __restrict__ lc, float* __restrict__ lqk,
                                      float* __restrict__ lv, const float* __restrict__ imp) {
    int row = blockIdx.x * 256 + threadIdx.x;   // 0..8191
    float w = imp[row];
    {
        float* p = lc + (long)row * NC;
        float mx = -1e30f;
        for (int i = 0; i < NC; i++) mx = fmaxf(mx, p[i]);
        float sum = 0.f;
        for (int i = 0; i < NC; i++) sum += __expf(p[i] - mx);
        float inv = w / sum;
        for (int i = 0; i < NC; i++) p[i] = __expf(p[i] - mx) * inv;
    }
    {
        float* p = lqk + (long)row * NQK;
        float mx = -1e30f;
        for (int i = 0; i < NQK; i++) mx = fmaxf(mx, p[i]);
        float sum = 0.f;
        for (int i = 0; i < NQK; i++) sum += __expf(p[i] - mx);
        float inv = w / sum;
        for (int i = 0; i < NQK; i++) p[i] = __expf(p[i] - mx) * inv;
    }
    {
        float* p = lv + (long)row * NV;
        float mx = -1e30f;
        for (int i = 0; i < NV; i++) mx = fmaxf(mx, p[i]);
        float sum = 0.f;
        for (int i = 0; i < NV; i++) sum += __expf(p[i] - mx);
        float inv = w / sum;
        for (int i = 0; i < NV; i++) p[i] = __expf(p[i] - mx) * inv;
    }
}

// ---- deterministic per-batch reduction over S ----
__global__ void router_reduce_kernel(const float* __restrict__ lc, const float* __restrict__ lqk,
                                     const float* __restrict__ lv, float* __restrict__ acc) {
    int b = blockIdx.x, t = threadIdx.x;   // 128 threads
    float s = 0.f;
    if (t < 64) {
        for (int i = 0; i < SEQ; i++) s += lc[((long)b * SEQ + i) * NC + t];
    } else if (t < 96) {
        int n = t - 64;
        for (int i = 0; i < SEQ; i++) s += lqk[((long)b * SEQ + i) * NQK + n];
    } else {
        int n = t - 96;
        for (int i = 0; i < SEQ; i++) s += lv[((long)b * SEQ + i) * NV + n];
    }
    acc[b * 128 + t] = s;
}

// ---- top-k select + renormalize; thread g in {0:c,1:qk,2:v} ----
__global__ void topk_kernel(const float* __restrict__ acc, int* __restrict__ idxo,
                            float* __restrict__ valo) {
    int b = blockIdx.x, g = threadIdx.x;
    if (g >= 3) return;
    const int off[3] = {0, 64, 96};
    const int nn[3]  = {64, 32, 32};
    const int kk[3]  = {8, 4, 6};
    float v[64];
    const float* a = acc + b * 128 + off[g];
    int n = nn[g], k = kk[g];
    for (int i = 0; i < n; i++) v[i] = a[i];
    float sum = 0.f;
    for (int j = 0; j < k; j++) {
        int best = 0;
        float bv = v[0];
        for (int i = 1; i < n; i++) if (v[i] > bv) { bv = v[i]; best = i; }
        idxo[(b * 3 + g) * 8 + j] = best;
        valo[(b * 3 + g) * 8 + j] = bv;
        sum += bv;
        v[best] = -1e30f;
    }
    float inv = 1.f / (sum + 1e-8f);
    for (int j = 0; j < k; j++) valo[(b * 3 + g) * 8 + j] *= inv;
}

// ---- sparse mixing: out[b] = sum_j val[j] * table[idx[j]]  (131072 floats each) ----
__global__ void mix_kernel(const float* __restrict__ table, const int* __restrict__ idx,
                           const float* __restrict__ val, int k, int g,
                           float* __restrict__ out) {
    int b = blockIdx.y;
    long e = ((long)blockIdx.x * 256 + threadIdx.x) * 4;
    const int* id = idx + (b * 3 + g) * 8;
    const float* vl = val + (b * 3 + g) * 8;
    float4 s = make_float4(0.f, 0.f, 0.f, 0.f);
    for (int j = 0; j < k; j++) {
        float w = vl[j];
        float4 t = *(const float4*)(table + (long)id[j] * 131072 + e);
        s.x += w * t.x; s.y += w * t.y; s.z += w * t.z; s.w += w * t.w;
    }
    *(float4*)(out + (long)b * 131072 + e) = s;
}

// ---------------- flash attention, 64x64 tiles, K == Q ----------------
__global__ void __launch_bounds__(256) flash_attn_kernel(const float* __restrict__ Q,
                                                         const float* __restrict__ V,
                                                         float* __restrict__ O) {
    extern __shared__ float smf[];
    float* Qs  = smf;            // [64][65]
    float* Ks  = Qs + 64 * 65;
    float* Vs  = Ks + 64 * 65;
    float* P   = Vs + 64 * 65;
    float* m_s = P + 64 * 65;
    float* l_s = m_s + 64;
    float* a_s = l_s + 64;

    const int qt = blockIdx.x, h = blockIdx.y, b = blockIdx.z;
    const int tid = threadIdx.x;
    const int tx = tid & 15, ty = tid >> 4;
    const long ho = (long)h * DH;
    const long bq = (long)b * SEQ + qt * 64;

    {
        const int r0 = tid >> 4;
        const int c4 = (tid & 15) * 4;
#pragma unroll
        for (int rr = r0; rr < 64; rr += 16) {
            float4 v = *(const float4*)(Q + (bq + rr) * DM + ho + c4);
            Qs[rr * 65 + c4 + 0] = v.x; Qs[rr * 65 + c4 + 1] = v.y;
            Qs[rr * 65 + c4 + 2] = v.z; Qs[rr * 65 + c4 + 3] = v.w;
        }
    }
    if (tid < 64) { m_s[tid] = -1e30f; l_s[tid] = 0.f; }
    float acc[4][4] = {};
    __syncthreads();

    for (int kt = 0; kt <= qt; kt++) {
        const long bk = (long)b * SEQ + kt * 64;
        {
            const int r0 = tid >> 4;
            const int c4 = (tid & 15) * 4;
#pragma unroll
            for (int rr = r0; rr < 64; rr += 16) {
                float4 kv = *(const float4*)(Q + (bk + rr) * DM + ho + c4);  // K == Q
                Ks[rr * 65 + c4 + 0] = kv.x; Ks[rr * 65 + c4 + 1] = kv.y;
                Ks[rr * 65 + c4 + 2] = kv.z; Ks[rr * 65 + c4 + 3] = kv.w;
                float4 vv = *(const float4*)(V + (bk + rr) * DM + ho + c4);
                Vs[rr * 65 + c4 + 0] = vv.x; Vs[rr * 65 + c4 + 1] = vv.y;
                Vs[rr * 65 + c4 + 2] = vv.z; Vs[rr * 65 + c4 + 3] = vv.w;
            }
        }
        __syncthreads();
        // scores
        float s[4][4] = {};
#pragma unroll 8
        for (int kk = 0; kk < 64; kk++) {
            float a[4], bb[4];
#pragma unroll
            for (int i = 0; i < 4; i++) a[i] = Qs[(ty * 4 + i) * 65 + kk];
#pragma unroll
            for (int j = 0; j < 4; j++) bb[j] = Ks[(tx * 4 + j) * 65 + kk];
#pragma unroll
            for (int i = 0; i < 4; i++)
#pragma unroll
                for (int j = 0; j < 4; j++)
                    s[i][j] += a[i] * bb[j];
        }
#pragma unroll
        for (int i = 0; i < 4; i++)
#pragma unroll
            for (int j = 0; j < 4; j++)
                P[(ty * 4 + i) * 65 + tx * 4 + j] = s[i][j] * 0.125f;
        __syncthreads();
        // online softmax (4 threads per row)
        {
            const int row = tid >> 2, part = tid & 3;
            const int qg = qt * 64 + row;
            const int cb = part * 16;
            float mx = -1e30f;
            float vals[16];
#pragma unroll
            for (int c = 0; c < 16; c++) {
                float sv = P[row * 65 + cb + c];
                if (kt * 64 + cb + c > qg) sv = -1e30f;
                vals[c] = sv;
                mx = fmaxf(mx, sv);
            }
            mx = fmaxf(mx, __shfl_xor_sync(0xffffffffu, mx, 1));
            mx = fmaxf(mx, __shfl_xor_sync(0xffffffffu, mx, 2));
            const float m_old = m_s[row];
            const float m_new = fmaxf(m_old, mx);
            float sum = 0.f;
#pragma unroll
            for (int c = 0; c < 16; c++) {
                float p = __expf(vals[c] - m_new);
                P[row * 65 + cb + c] = p;
                sum += p;
            }
            sum += __shfl_xor_sync(0xffffffffu, sum, 1);
            sum += __shfl_xor_sync(0xffffffffu, sum, 2);
            if (part == 0) {
                float alpha = __expf(m_old - m_new);
                l_s[row] = l_s[row] * alpha + sum;
                m_s[row] = m_new;
                a_s[row] = alpha;
            }
        }
        __syncthreads();
        // P @ V accumulate
        {
            float alr[4];
#pragma unroll
            for (int i = 0; i < 4; i++) alr[i] = a_s[ty * 4 + i];
#pragma unroll
            for (int i = 0; i < 4; i++)
#pragma unroll
                for (int j = 0; j < 4; j++)
                    acc[i][j] *= alr[i];
#pragma unroll 8
            for (int kk = 0; kk < 64; kk++) {
                float p[4], v[4];
#pragma unroll
                for (int i = 0; i < 4; i++) p[i] = P[(ty * 4 + i) * 65 + kk];
#pragma unroll
                for (int j = 0; j < 4; j++) v[j] = Vs[kk * 65 + tx * 4 + j];
#pragma unroll
                for (int i = 0; i < 4; i++)
#pragma unroll
                    for (int j = 0; j < 4; j++)
                        acc[i][j] += p[i] * v[j];
            }
        }
        __syncthreads();
    }
#pragma unroll
    for (int i = 0; i < 4; i++) {
        float inv = 1.f / l_s[ty * 4 + i];
        float4 o;
        o.x = acc[i][0] * inv; o.y = acc[i][1] * inv;
        o.z = acc[i][2] * inv; o.w = acc[i][3] * inv;
        *(float4*)(O + (bq + ty * 4 + i) * DM + ho + tx * 4) = o;
    }
}

// ---------------- host ----------------
extern "C" void kernel_launch(void* const* d_in, const int* in_sizes, int n_in,
                              void* d_out, int out_size) {
    const float* x   = (const float*)d_in[0];
    const float* imp = (const float*)d_in[1];
    const float* Wc  = (const float*)d_in[2];
    const float* Wqk = (const float*)d_in[3];
    const float* Wv  = (const float*)d_in[4];
    const float* cn  = (const float*)d_in[5];
    const float* eQK = (const float*)d_in[6];
    const float* eV  = (const float*)d_in[7];
    const float* Wo  = (const float*)d_in[8];
    float* out = (float*)d_out;

    float *logc, *logqk, *logv, *acc, *val, *sc, *eqk, *ev, *h, *Qb, *Vb, *att;
    int* idx;
    cudaGetSymbolAddress((void**)&logc, g_logc);
    cudaGetSymbolAddress((void**)&logqk, g_logqk);
    cudaGetSymbolAddress((void**)&logv, g_logv);
    cudaGetSymbolAddress((void**)&acc, g_acc);
    cudaGetSymbolAddress((void**)&idx, g_idx);
    cudaGetSymbolAddress((void**)&val, g_val);
    cudaGetSymbolAddress((void**)&sc, g_sc);
    cudaGetSymbolAddress((void**)&eqk, g_eqk);
    cudaGetSymbolAddress((void**)&ev, g_ev);
    cudaGetSymbolAddress((void**)&h, g_h);
    cudaGetSymbolAddress((void**)&Qb, g_Q);
    cudaGetSymbolAddress((void**)&Vb, g_V);
    cudaGetSymbolAddress((void**)&att, g_att);

    // 1) router logits: x[8192,1024] @ W^T
    gemm64<true><<<dim3(1, 128, 1), 256>>>(x, Wc,  logc,  BATCH * SEQ, NC,  DM, 0, 0, 0);
    gemm64<true><<<dim3(1, 128, 1), 256>>>(x, Wqk, logqk, BATCH * SEQ, NQK, DM, 0, 0, 0);
    gemm64<true><<<dim3(1, 128, 1), 256>>>(x, Wv,  logv,  BATCH * SEQ, NV,  DM, 0, 0, 0);

    // 2) softmax * importance (in place), deterministic reduce, top-k
    softmax_weight_kernel<<<32, 256>>>(logc, logqk, logv, imp);
    router_reduce_kernel<<<BATCH, 128>>>(logc, logqk, logv, acc);
    topk_kernel<<<BATCH, 3>>>(acc, idx, val);

    // 3) sparse mixing of neuron banks
    mix_kernel<<<dim3(128, BATCH), 256>>>(cn,  idx, val, KC,  0, sc);
    mix_kernel<<<dim3(128, BATCH), 256>>>(eQK, idx, val, KQK, 1, eqk);
    mix_kernel<<<dim3(128, BATCH), 256>>>(eV,  idx, val, KV,  2, ev);

    // 4) h = x @ sc   [1024,1024]@[1024,128] batched
    gemm64<false><<<dim3(2, 16, BATCH), 256>>>(x, sc, h, SEQ, RANK, DM,
                                               (long)SEQ * DM, (long)DM * RANK, (long)SEQ * RANK);

    // 5) Q = h @ eqk, V = h @ ev   [1024,128]@[128,1024] batched
    gemm128<false><<<dim3(8, 8, BATCH), 256>>>(h, eqk, Qb, SEQ, DM, RANK,
                                               (long)SEQ * RANK, (long)RANK * DM, (long)SEQ * DM);
    gemm128<false><<<dim3(8, 8, BATCH), 256>>>(h, ev, Vb, SEQ, DM, RANK,
                                               (long)SEQ * RANK, (long)RANK * DM, (long)SEQ * DM);

    // 6) causal attention (K == Q)
    cudaFuncSetAttribute(flash_attn_kernel, cudaFuncAttributeMaxDynamicSharedMemorySize, 67328);
    flash_attn_kernel<<<dim3(SEQ / 64, NH, BATCH), 256, 67328>>>(Qb, Vb, att);

    // 7) out = att @ Wo^T   [8192,1024]@[1024,1024]^T
    gemm128<true><<<dim3(8, 64, 1), 256>>>(att, Wo, out, BATCH * SEQ, DM, DM, 0, 0, 0);
}

// round 4
// speedup vs baseline: 1.7984x; 1.7984x over previous
#include <cuda_runtime.h>
#include <cuda_bf16.h>
#include <math.h>
#include <stdint.h>

#define BATCH 8
#define SEQ 1024
#define DM 1024
#define NH 16
#define DH 64
#define RANK 128
#define NC 64
#define NQK 32
#define NV 32

typedef __nv_bfloat16 bf16;

// ---------------- scratch (device globals) ----------------
__device__ bf16 g_xhi[BATCH * SEQ * DM], g_xlo[BATCH * SEQ * DM];
__device__ bf16 g_wohi[DM * DM], g_wolo[DM * DM];
__device__ float g_logc[BATCH * SEQ * NC];
__device__ float g_logqk[BATCH * SEQ * NQK];
__device__ float g_logv[BATCH * SEQ * NV];
__device__ float g_part[64 * 128];
__device__ int   g_idx[BATCH * 3 * 8];
__device__ float g_val[BATCH * 3 * 8];
__device__ bf16 g_schi[BATCH * RANK * DM], g_sclo[BATCH * RANK * DM];     // scT [r][d]
__device__ bf16 g_eqkhi[BATCH * DM * RANK], g_eqklo[BATCH * DM * RANK];   // eqkT [d][r]
__device__ bf16 g_evhi[BATCH * DM * RANK], g_evlo[BATCH * DM * RANK];
__device__ bf16 g_hhi[BATCH * SEQ * RANK], g_hlo[BATCH * SEQ * RANK];
__device__ bf16 g_qhi[BATCH * SEQ * DM], g_qlo[BATCH * SEQ * DM];
__device__ bf16 g_vhi[BATCH * SEQ * DM], g_vlo[BATCH * SEQ * DM];
__device__ bf16 g_atthi[BATCH * SEQ * DM], g_attlo[BATCH * SEQ * DM];

// ---------------- helpers ----------------
__device__ __forceinline__ unsigned pk2(float a, float b) {
    bf16 ha = __float2bfloat16_rn(a), hb = __float2bfloat16_rn(b);
    return ((unsigned)*(unsigned short*)&hb << 16) | *(unsigned short*)&ha;
}
__device__ __forceinline__ void split2(float a, float b, unsigned& hi, unsigned& lo) {
    bf16 ha = __float2bfloat16_rn(a), hb = __float2bfloat16_rn(b);
    hi = ((unsigned)*(unsigned short*)&hb << 16) | *(unsigned short*)&ha;
    lo = pk2(a - __bfloat162float(ha), b - __bfloat162float(hb));
}
__device__ __forceinline__ void mma16816(float* c, const unsigned* a, const unsigned* b) {
    asm volatile(
        "mma.sync.aligned.m16n8k16.row.col.f32.bf16.bf16.f32 "
        "{%0,%1,%2,%3},{%4,%5,%6,%7},{%8,%9},{%0,%1,%2,%3};\n"
        : "+f"(c[0]), "+f"(c[1]), "+f"(c[2]), "+f"(c[3])
        : "r"(a[0]), "r"(a[1]), "r"(a[2]), "r"(a[3]), "r"(b[0]), "r"(b[1]));
}

// ---------------- split fp32 -> bf16 hi/lo ----------------
__global__ void split_kernel(const float* __restrict__ src, bf16* __restrict__ hi,
                             bf16* __restrict__ lo, long n) {
    long i = ((long)blockIdx.x * 256 + threadIdx.x) * 4;
    if (i >= n) return;
    float4 v = *(const float4*)(src + i);
    unsigned h0, l0, h1, l1;
    split2(v.x, v.y, h0, l0);
    split2(v.z, v.w, h1, l1);
    *(uint2*)(hi + i) = make_uint2(h0, h1);
    *(uint2*)(lo + i) = make_uint2(l0, l1);
}

// ---------------- router GEMM (fp32, small) ----------------
__global__ void __launch_bounds__(256) gemm64t(const float* __restrict__ A,
                                               const float* __restrict__ B,
                                               float* __restrict__ C,
                                               int M, int N, int K) {
    __shared__ float As[16][64];
    __shared__ float Bs[16][64];
    const int m0 = blockIdx.y * 64;
    const int tid = threadIdx.x, tx = tid & 15, ty = tid >> 4;
    float acc[4][4] = {};
    for (int k0 = 0; k0 < K; k0 += 16) {
        {
            int r = tid >> 2, c = (tid & 3) * 4;
            float4 v = *(const float4*)(A + (long)(m0 + r) * K + k0 + c);
            As[c + 0][r] = v.x; As[c + 1][r] = v.y; As[c + 2][r] = v.z; As[c + 3][r] = v.w;
        }
        {
            int r = tid >> 2, c = (tid & 3) * 4;
            float4 v = make_float4(0.f, 0.f, 0.f, 0.f);
            if (r < N) v = *(const float4*)(B + (long)r * K + k0 + c);
            Bs[c + 0][r] = v.x; Bs[c + 1][r] = v.y; Bs[c + 2][r] = v.z; Bs[c + 3][r] = v.w;
        }
        __syncthreads();
#pragma unroll
        for (int kk = 0; kk < 16; kk++) {
            float a[4], bb[4];
            *(float4*)a  = *(const float4*)&As[kk][ty * 4];
            *(float4*)bb = *(const float4*)&Bs[kk][tx * 4];
#pragma unroll
            for (int i = 0; i < 4; i++)
#pragma unroll
                for (int j = 0; j < 4; j++)
                    acc[i][j] += a[i] * bb[j];
        }
        __syncthreads();
    }
#pragma unroll
    for (int i = 0; i < 4; i++) {
        int m = m0 + ty * 4 + i;
#pragma unroll
        for (int j = 0; j < 4; j++) {
            int n = tx * 4 + j;
            if (n < N) C[(long)m * N + n] = acc[i][j];
        }
    }
}

// ---- fused softmax * importance + deterministic partial reduce ----
__global__ void __launch_bounds__(256) router_post(const float* __restrict__ lc,
                                                   const float* __restrict__ lqk,
                                                   const float* __restrict__ lv,
                                                   const float* __restrict__ imp,
                                                   float* __restrict__ part) {
    int blk = blockIdx.x, bb = blk >> 3, sg = blk & 7;
    int w = threadIdx.x >> 5, lane = threadIdx.x & 31;
    long rowbase = (long)bb * SEQ + sg * 128 + w * 16;
    float aC0 = 0.f, aC1 = 0.f, aQ = 0.f, aV = 0.f;
    for (int it = 0; it < 16; it++) {
        long row = rowbase + it;
        float wi = imp[row];
        float c0 = lc[row * NC + lane], c1 = lc[row * NC + 32 + lane];
        float q0 = lqk[row * NQK + lane];
        float v0 = lv[row * NV + lane];
        float m = fmaxf(c0, c1);
#pragma unroll
        for (int o = 16; o >= 1; o >>= 1) m = fmaxf(m, __shfl_xor_sync(~0u, m, o));
        float e0 = __expf(c0 - m), e1 = __expf(c1 - m);
        float s = e0 + e1;
#pragma unroll
        for (int o = 16; o >= 1; o >>= 1) s += __shfl_xor_sync(~0u, s, o);
        float f = wi / s;
        aC0 += e0 * f; aC1 += e1 * f;
        m = q0;
#pragma unroll
        for (int o = 16; o >= 1; o >>= 1) m = fmaxf(m, __shfl_xor_sync(~0u, m, o));
        e0 = __expf(q0 - m);
        s = e0;
#pragma unroll
        for (int o = 16; o >= 1; o >>= 1) s += __shfl_xor_sync(~0u, s, o);
        aQ += e0 * wi / s;
        m = v0;
#pragma unroll
        for (int o = 16; o >= 1; o >>= 1) m = fmaxf(m, __shfl_xor_sync(~0u, m, o));
        e0 = __expf(v0 - m);
        s = e0;
#pragma unroll
        for (int o = 16; o >= 1; o >>= 1) s += __shfl_xor_sync(~0u, s, o);
        aV += e0 * wi / s;
    }
    __shared__ float ps[8][128];
    ps[w][lane] = aC0; ps[w][32 + lane] = aC1;
    ps[w][64 + lane] = aQ; ps[w][96 + lane] = aV;
    __syncthreads();
    int t = threadIdx.x;
    if (t < 128) {
        float s = 0.f;
#pragma unroll
        for (int ww = 0; ww < 8; ww++) s += ps[ww][t];
        part[blk * 128 + t] = s;
    }
}

// ---- final reduce + top-k (deterministic, fixed order) ----
__global__ void router_final(const float* __restrict__ part, int* __restrict__ idxo,
                             float* __restrict__ valo) {
    int b = blockIdx.x, t = threadIdx.x;  // 128 threads
    __shared__ float acc[128];
    float s = 0.f;
#pragma unroll
    for (int sg = 0; sg < 8; sg++) s += part[(b * 8 + sg) * 128 + t];
    acc[t] = s;
    __syncthreads();
    if (t < 3) {
        const int off[3] = {0, 64, 96};
        const int nn[3] = {64, 32, 32};
        const int kk[3] = {8, 4, 6};
        float v[64];
        int n = nn[t], k = kk[t];
        for (int i = 0; i < n; i++) v[i] = acc[off[t] + i];
        float sum = 0.f;
        for (int j = 0; j < k; j++) {
            int best = 0;
            float bv = v[0];
            for (int i = 1; i < n; i++) if (v[i] > bv) { bv = v[i]; best = i; }
            idxo[(b * 3 + t) * 8 + j] = best;
            valo[(b * 3 + t) * 8 + j] = bv;
            sum += bv;
            v[best] = -1e30f;
        }
        float inv = 1.f / (sum + 1e-8f);
        for (int j = 0; j < k; j++) valo[(b * 3 + t) * 8 + j] *= inv;
    }
}

// ---- sparse mix + transpose + split ----
__global__ void __launch_bounds__(256) mix_T_split(const float* __restrict__ table,
                                                   const int* __restrict__ idx,
                                                   const float* __restrict__ val,
                                                   int k, int g, int P, int Q,
                                                   bf16* __restrict__ outhi,
                                                   bf16* __restrict__ outlo) {
    __shared__ float tile[32][33];
    int b = blockIdx.z;
    int q0 = blockIdx.x * 32, p0 = blockIdx.y * 32;
    int tx = threadIdx.x, ty = threadIdx.y;
    const int* id = idx + (b * 3 + g) * 8;
    const float* vl = val + (b * 3 + g) * 8;
    float wj[8];
    int ij[8];
#pragma unroll
    for (int j = 0; j < 8; j++) { wj[j] = (j < k) ? vl[j] : 0.f; ij[j] = (j < k) ? id[j] : 0; }
#pragma unroll
    for (int ii = 0; ii < 4; ii++) {
        int p = p0 + ty + 8 * ii;
        float s = 0.f;
        for (int j = 0; j < k; j++)
            s += wj[j] * table[((long)ij[j] * P + p) * Q + q0 + tx];
        tile[ty + 8 * ii][tx] = s;
    }
    __syncthreads();
    bf16* oh = outhi + (long)b * P * Q;
    bf16* ol = outlo + (long)b * P * Q;
#pragma unroll
    for (int ii = 0; ii < 4; ii++) {
        int q = q0 + ty + 8 * ii, p = p0 + tx;
        float v = tile[tx][ty + 8 * ii];
        bf16 h = __float2bfloat16_rn(v);
        oh[(long)q * P + p] = h;
        ol[(long)q * P + p] = __float2bfloat16_rn(v - __bfloat162float(h));
    }
}

// ---------------- bf16x3 tensor-core GEMM: C = A @ B^T ----------------
template<bool SPLIT_OUT>
__global__ void __launch_bounds__(256) gemm_tc(
    const bf16* __restrict__ Ahi, const bf16* __restrict__ Alo,
    const bf16* __restrict__ Bhi, const bf16* __restrict__ Blo,
    float* __restrict__ C, bf16* __restrict__ Chi, bf16* __restrict__ Clo,
    int M, int N, int K, long sA, long sB, long sC)
{
    __shared__ bf16 Ash[128 * 40], Asl[128 * 40];
    __shared__ bf16 Bsh[128 * 40], Bsl[128 * 40];
    const int tid = threadIdx.x, lane = tid & 31, w = tid >> 5;
    const int g = lane >> 2, t = lane & 3;
    const int wm = (w >> 2) * 64, wn = (w & 3) * 32;
    const int m0 = blockIdx.y * 128, n0 = blockIdx.x * 128;
    Ahi += (long)blockIdx.z * sA; Alo += (long)blockIdx.z * sA;
    Bhi += (long)blockIdx.z * sB; Blo += (long)blockIdx.z * sB;
    // FIX (R3 bug): offset output pointers per batch
    if (C)   C   += (long)blockIdx.z * sC;
    if (Chi) Chi += (long)blockIdx.z * sC;
    if (Clo) Clo += (long)blockIdx.z * sC;

    float acc[4][4][4] = {};
    for (int k0 = 0; k0 < K; k0 += 32) {
#pragma unroll
        for (int c = 0; c < 2; c++) {
            int chunk = tid + 256 * c;
            int row = chunk >> 2, col = (chunk & 3) * 8;
            *(uint4*)&Ash[row * 40 + col] = *(const uint4*)(Ahi + (long)(m0 + row) * K + k0 + col);
            *(uint4*)&Asl[row * 40 + col] = *(const uint4*)(Alo + (long)(m0 + row) * K + k0 + col);
            *(uint4*)&Bsh[row * 40 + col] = *(const uint4*)(Bhi + (long)(n0 + row) * K + k0 + col);
            *(uint4*)&Bsl[row * 40 + col] = *(const uint4*)(Blo + (long)(n0 + row) * K + k0 + col);
        }
        __syncthreads();
#pragma unroll
        for (int ks = 0; ks < 2; ks++) {
            const int kk = ks * 16;
            unsigned ah[4][4], al[4][4], bh[4][2], bl[4][2];
#pragma unroll
            for (int i = 0; i < 4; i++) {
                int r = wm + 16 * i + g;
                ah[i][0] = *(unsigned*)&Ash[r * 40 + kk + 2 * t];
                ah[i][1] = *(unsigned*)&Ash[(r + 8) * 40 + kk + 2 * t];
                ah[i][2] = *(unsigned*)&Ash[r * 40 + kk + 8 + 2 * t];
                ah[i][3] = *(unsigned*)&Ash[(r + 8) * 40 + kk + 8 + 2 * t];
                al[i][0] = *(unsigned*)&Asl[r * 40 + kk + 2 * t];
                al[i][1] = *(unsigned*)&Asl[(r + 8) * 40 + kk + 2 * t];
                al[i][2] = *(unsigned*)&Asl[r * 40 + kk + 8 + 2 * t];
                al[i][3] = *(unsigned*)&Asl[(r + 8) * 40 + kk + 8 + 2 * t];
            }
#pragma unroll
            for (int j = 0; j < 4; j++) {
                int n = wn + 8 * j + g;
                bh[j][0] = *(unsigned*)&Bsh[n * 40 + kk + 2 * t];
                bh[j][1] = *(unsigned*)&Bsh[n * 40 + kk + 8 + 2 * t];
                bl[j][0] = *(unsigned*)&Bsl[n * 40 + kk + 2 * t];
                bl[j][1] = *(unsigned*)&Bsl[n * 40 + kk + 8 + 2 * t];
            }
#pragma unroll
            for (int i = 0; i < 4; i++)
#pragma unroll
                for (int j = 0; j < 4; j++) {
                    mma16816(acc[i][j], ah[i], bh[j]);
                    mma16816(acc[i][j], ah[i], bl[j]);
                    mma16816(acc[i][j], al[i], bh[j]);
                }
        }
        __syncthreads();
    }
    const int ldc = N;
#pragma unroll
    for (int i = 0; i < 4; i++) {
        int r = m0 + wm + 16 * i + g;
#pragma unroll
        for (int j = 0; j < 4; j++) {
            int cidx = n0 + wn + 8 * j + 2 * t;
            if (SPLIT_OUT) {
                unsigned hi, lo;
                split2(acc[i][j][0], acc[i][j][1], hi, lo);
                *(unsigned*)&Chi[(long)r * ldc + cidx] = hi;
                *(unsigned*)&Clo[(long)r * ldc + cidx] = lo;
                split2(acc[i][j][2], acc[i][j][3], hi, lo);
                *(unsigned*)&Chi[(long)(r + 8) * ldc + cidx] = hi;
                *(unsigned*)&Clo[(long)(r + 8) * ldc + cidx] = lo;
            } else {
                *(float2*)&C[(long)r * ldc + cidx] = make_float2(acc[i][j][0], acc[i][j][1]);
                *(float2*)&C[(long)(r + 8) * ldc + cidx] = make_float2(acc[i][j][2], acc[i][j][3]);
            }
        }
    }
}

// ---------------- tensor-core flash attention (K == Q), bf16x3 ----------------
__global__ void __launch_bounds__(128) attn_tc(const bf16* __restrict__ Qh_g,
                                               const bf16* __restrict__ Ql_g,
                                               const bf16* __restrict__ Vh_g,
                                               const bf16* __restrict__ Vl_g,
                                               bf16* __restrict__ Ohi,
                                               bf16* __restrict__ Olo) {
    extern __shared__ bf16 sm[];
    bf16* Qs_h = sm;
    bf16* Qs_l = Qs_h + 64 * 72;
    bf16* Ks_h = Qs_l + 64 * 72;
    bf16* Ks_l = Ks_h + 64 * 72;
    bf16* Vs_h = Ks_l + 64 * 72;
    bf16* Vs_l = Vs_h + 64 * 72;

    const int qt = blockIdx.x, h = blockIdx.y, b = blockIdx.z;
    const int tid = threadIdx.x, lane = tid & 31, w = tid >> 5;
    const int g = lane >> 2, t = lane & 3;
    const long ho = (long)h * DH;
    const long bq = (long)b * SEQ + qt * 64;

#pragma unroll
    for (int c = 0; c < 4; c++) {
        int chunk = tid + 128 * c;
        int row = chunk >> 3, col = (chunk & 7) * 8;
        *(uint4*)&Qs_h[row * 72 + col] = *(const uint4*)(Qh_g + (bq + row) * DM + ho + col);
        *(uint4*)&Qs_l[row * 72 + col] = *(const uint4*)(Ql_g + (bq + row) * DM + ho + col);
    }

    float o[8][4] = {};
    float m0 = -1e30f, m1 = -1e30f, l0 = 0.f, l1 = 0.f;

    for (int kt = 0; kt <= qt; kt++) {
        const long bk = (long)b * SEQ + kt * 64;
#pragma unroll
        for (int c = 0; c < 4; c++) {
            int chunk = tid + 128 * c;
            int row = chunk >> 3, col = (chunk & 7) * 8;
            *(uint4*)&Ks_h[row * 72 + col] = *(const uint4*)(Qh_g + (bk + row) * DM + ho + col);
            *(uint4*)&Ks_l[row * 72 + col] = *(const uint4*)(Ql_g + (bk + row) * DM + ho + col);
            *(uint4*)&Vs_h[row * 72 + col] = *(const uint4*)(Vh_g + (bk + row) * DM + ho + col);
            *(uint4*)&Vs_l[row * 72 + col] = *(const uint4*)(Vl_g + (bk + row) * DM + ho + col);
        }
        __syncthreads();

        float s[8][4] = {};
#pragma unroll
        for (int kk = 0; kk < 4; kk++) {
            const int k16 = kk * 16;
            unsigned qa_h[4], qa_l[4];
            const int r = w * 16 + g;
            qa_h[0] = *(unsigned*)&Qs_h[r * 72 + k16 + 2 * t];
            qa_h[1] = *(unsigned*)&Qs_h[(r + 8) * 72 + k16 + 2 * t];
            qa_h[2] = *(unsigned*)&Qs_h[r * 72 + k16 + 8 + 2 * t];
            qa_h[3] = *(unsigned*)&Qs_h[(r + 8) * 72 + k16 + 8 + 2 * t];
            qa_l[0] = *(unsigned*)&Qs_l[r * 72 + k16 + 2 * t];
            qa_l[1] = *(unsigned*)&Qs_l[(r + 8) * 72 + k16 + 2 * t];
            qa_l[2] = *(unsigned*)&Qs_l[r * 72 + k16 + 8 + 2 * t];
            qa_l[3] = *(unsigned*)&Qs_l[(r + 8) * 72 + k16 + 8 + 2 * t];
#pragma unroll
            for (int j = 0; j < 8; j++) {
                const int n = 8 * j + g;
                unsigned kb_h[2], kb_l[2];
                kb_h[0] = *(unsigned*)&Ks_h[n * 72 + k16 + 2 * t];
                kb_h[1] = *(unsigned*)&Ks_h[n * 72 + k16 + 8 + 2 * t];
                kb_l[0] = *(unsigned*)&Ks_l[n * 72 + k16 + 2 * t];
                kb_l[1] = *(unsigned*)&Ks_l[n * 72 + k16 + 8 + 2 * t];
                mma16816(s[j], qa_h, kb_h);
                mma16816(s[j], qa_h, kb_l);
                mma16816(s[j], qa_l, kb_h);
            }
        }
        const bool diag = (kt == qt);
        const int lim0 = w * 16 + g, lim1 = lim0 + 8;
#pragma unroll
        for (int j = 0; j < 8; j++) {
#pragma unroll
            for (int e = 0; e < 4; e++) s[j][e] *= 0.125f;
            if (diag) {
                int col = 8 * j + 2 * t;
                if (col > lim0) s[j][0] = -1e30f;
                if (col + 1 > lim0) s[j][1] = -1e30f;
                if (col > lim1) s[j][2] = -1e30f;
                if (col + 1 > lim1) s[j][3] = -1e30f;
            }
        }
        float mx0 = -1e30f, mx1 = -1e30f;
#pragma unroll
        for (int j = 0; j < 8; j++) {
            mx0 = fmaxf(mx0, fmaxf(s[j][0], s[j][1]));
            mx1 = fmaxf(mx1, fmaxf(s[j][2], s[j][3]));
        }
        mx0 = fmaxf(mx0, __shfl_xor_sync(~0u, mx0, 1));
        mx0 = fmaxf(mx0, __shfl_xor_sync(~0u, mx0, 2));
        mx1 = fmaxf(mx1, __shfl_xor_sync(~0u, mx1, 1));
        mx1 = fmaxf(mx1, __shfl_xor_sync(~0u, mx1, 2));
        float mn0 = fmaxf(m0, mx0), mn1 = fmaxf(m1, mx1);
        float al0 = __expf(m0 - mn0), al1 = __expf(m1 - mn1);
        m0 = mn0; m1 = mn1;
        float sum0 = 0.f, sum1 = 0.f;
#pragma unroll
        for (int j = 0; j < 8; j++) {
            s[j][0] = __expf(s[j][0] - mn0); sum0 += s[j][0];
            s[j][1] = __expf(s[j][1] - mn0); sum0 += s[j][1];
            s[j][2] = __expf(s[j][2] - mn1); sum1 += s[j][2];
            s[j][3] = __expf(s[j][3] - mn1); sum1 += s[j][3];
        }
        sum0 += __shfl_xor_sync(~0u, sum0, 1);
        sum0 += __shfl_xor_sync(~0u, sum0, 2);
        sum1 += __shfl_xor_sync(~0u, sum1, 1);
        sum1 += __shfl_xor_sync(~0u, sum1, 2);
        l0 = l0 * al0 + sum0;
        l1 = l1 * al1 + sum1;
#pragma unroll
        for (int j = 0; j < 8; j++) {
            o[j][0] *= al0; o[j][1] *= al0;
            o[j][2] *= al1; o[j][3] *= al1;
        }
#pragma unroll
        for (int kk = 0; kk < 4; kk++) {
            unsigned pa_h[4], pa_l[4];
            split2(s[2 * kk][0], s[2 * kk][1], pa_h[0], pa_l[0]);
            split2(s[2 * kk][2], s[2 * kk][3], pa_h[1], pa_l[1]);
            split2(s[2 * kk + 1][0], s[2 * kk + 1][1], pa_h[2], pa_l[2]);
            split2(s[2 * kk + 1][2], s[2 * kk + 1][3], pa_h[3], pa_l[3]);
            const int kb = 16 * kk + 2 * t;
#pragma unroll
            for (int j = 0; j < 8; j++) {
                const int n = 8 * j + g;
                unsigned vb_h[2], vb_l[2];
                unsigned short x0, x1;
                x0 = *(const unsigned short*)&Vs_h[kb * 72 + n];
                x1 = *(const unsigned short*)&Vs_h[(kb + 1) * 72 + n];
                vb_h[0] = x0 | ((unsigned)x1 << 16);
                x0 = *(const unsigned short*)&Vs_h[(kb + 8) * 72 + n];
                x1 = *(const unsigned short*)&Vs_h[(kb + 9) * 72 + n];
                vb_h[1] = x0 | ((unsigned)x1 << 16);
                x0 = *(const unsigned short*)&Vs_l[kb * 72 + n];
                x1 = *(const unsigned short*)&Vs_l[(kb + 1) * 72 + n];
                vb_l[0] = x0 | ((unsigned)x1 << 16);
                x0 = *(const unsigned short*)&Vs_l[(kb + 8) * 72 + n];
                x1 = *(const unsigned short*)&Vs_l[(kb + 9) * 72 + n];
                vb_l[1] = x0 | ((unsigned)x1 << 16);
                mma16816(o[j], pa_h, vb_h);
                mma16816(o[j], pa_h, vb_l);
                mma16816(o[j], pa_l, vb_h);
            }
        }
        __syncthreads();
    }
    const float il0 = 1.f / l0, il1 = 1.f / l1;
    const long row0 = bq + w * 16 + g, row1 = row0 + 8;
#pragma unroll
    for (int j = 0; j < 8; j++) {
        const long col = ho + 8 * j + 2 * t;
        unsigned hi, lo;
        split2(o[j][0] * il0, o[j][1] * il0, hi, lo);
        *(unsigned*)&Ohi[row0 * DM + col] = hi;
        *(unsigned*)&Olo[row0 * DM + col] = lo;
        split2(o[j][2] * il1, o[j][3] * il1, hi, lo);
        *(unsigned*)&Ohi[row1 * DM + col] = hi;
        *(unsigned*)&Olo[row1 * DM + col] = lo;
    }
}

// ---------------- host ----------------
extern "C" void kernel_launch(void* const* d_in, const int* in_sizes, int n_in,
                              void* d_out, int out_size) {
    const float* x   = (const float*)d_in[0];
    const float* imp = (const float*)d_in[1];
    const float* Wc  = (const float*)d_in[2];
    const float* Wqk = (const float*)d_in[3];
    const float* Wv  = (const float*)d_in[4];
    const float* cn  = (const float*)d_in[5];
    const float* eQK = (const float*)d_in[6];
    const float* eV  = (const float*)d_in[7];
    const float* Wo  = (const float*)d_in[8];
    float* out = (float*)d_out;

    bf16 *xhi, *xlo, *wohi, *wolo, *schi, *sclo, *eqkhi, *eqklo, *evhi, *evlo;
    bf16 *hhi, *hlo, *qhi, *qlo, *vhi, *vlo, *atthi, *attlo;
    float *logc, *logqk, *logv, *part, *val;
    int* idx;
    cudaGetSymbolAddress((void**)&xhi, g_xhi);     cudaGetSymbolAddress((void**)&xlo, g_xlo);
    cudaGetSymbolAddress((void**)&wohi, g_wohi);   cudaGetSymbolAddress((void**)&wolo, g_wolo);
    cudaGetSymbolAddress((void**)&logc, g_logc);   cudaGetSymbolAddress((void**)&logqk, g_logqk);
    cudaGetSymbolAddress((void**)&logv, g_logv);   cudaGetSymbolAddress((void**)&part, g_part);
    cudaGetSymbolAddress((void**)&idx, g_idx);     cudaGetSymbolAddress((void**)&val, g_val);
    cudaGetSymbolAddress((void**)&schi, g_schi);   cudaGetSymbolAddress((void**)&sclo, g_sclo);
    cudaGetSymbolAddress((void**)&eqkhi, g_eqkhi); cudaGetSymbolAddress((void**)&eqklo, g_eqklo);
    cudaGetSymbolAddress((void**)&evhi, g_evhi);   cudaGetSymbolAddress((void**)&evlo, g_evlo);
    cudaGetSymbolAddress((void**)&hhi, g_hhi);     cudaGetSymbolAddress((void**)&hlo, g_hlo);
    cudaGetSymbolAddress((void**)&qhi, g_qhi);     cudaGetSymbolAddress((void**)&qlo, g_qlo);
    cudaGetSymbolAddress((void**)&vhi, g_vhi);     cudaGetSymbolAddress((void**)&vlo, g_vlo);
    cudaGetSymbolAddress((void**)&atthi, g_atthi); cudaGetSymbolAddress((void**)&attlo, g_attlo);

    // splits
    split_kernel<<<8192, 256>>>(x, xhi, xlo, (long)BATCH * SEQ * DM);
    split_kernel<<<1024, 256>>>(Wo, wohi, wolo, (long)DM * DM);

    // routers (fp32)
    gemm64t<<<dim3(1, 128), 256>>>(x, Wc,  logc,  BATCH * SEQ, NC,  DM);
    gemm64t<<<dim3(1, 128), 256>>>(x, Wqk, logqk, BATCH * SEQ, NQK, DM);
    gemm64t<<<dim3(1, 128), 256>>>(x, Wv,  logv,  BATCH * SEQ, NV,  DM);
    router_post<<<64, 256>>>(logc, logqk, logv, imp, part);
    router_final<<<BATCH, 128>>>(part, idx, val);

    // sparse mixes (transposed + split)
    mix_T_split<<<dim3(RANK / 32, DM / 32, BATCH), dim3(32, 8)>>>(cn,  idx, val, 8, 0, DM, RANK, schi, sclo);
    mix_T_split<<<dim3(DM / 32, RANK / 32, BATCH), dim3(32, 8)>>>(eQK, idx, val, 4, 1, RANK, DM, eqkhi, eqklo);
    mix_T_split<<<dim3(DM / 32, RANK / 32, BATCH), dim3(32, 8)>>>(eV,  idx, val, 6, 2, RANK, DM, evhi, evlo);

    // h = x @ scT^T  [1024x128], K=1024
    gemm_tc<true><<<dim3(1, 8, BATCH), 256>>>(xhi, xlo, schi, sclo,
        nullptr, hhi, hlo, SEQ, RANK, DM,
        (long)SEQ * DM, (long)RANK * DM, (long)SEQ * RANK);

    // Q = h @ eqkT^T, V = h @ evT^T  [1024x1024], K=128
    gemm_tc<true><<<dim3(8, 8, BATCH), 256>>>(hhi, hlo, eqkhi, eqklo,
        nullptr, qhi, qlo, SEQ, DM, RANK,
        (long)SEQ * RANK, (long)DM * RANK, (long)SEQ * DM);
    gemm_tc<true><<<dim3(8, 8, BATCH), 256>>>(hhi, hlo, evhi, evlo,
        nullptr, vhi, vlo, SEQ, DM, RANK,
        (long)SEQ * RANK, (long)DM * RANK, (long)SEQ * DM);

    // attention
    cudaFuncSetAttribute(attn_tc, cudaFuncAttributeMaxDynamicSharedMemorySize, 55296);
    attn_tc<<<dim3(SEQ / 64, NH, BATCH), 128, 55296>>>(qhi, qlo, vhi, vlo, atthi, attlo);

    // out = att @ Wo^T  [8192x1024], K=1024, fp32 out
    gemm_tc<false><<<dim3(8, 64, 1), 256>>>(atthi, attlo, wohi, wolo,
        out, nullptr, nullptr, BATCH * SEQ, DM, DM, 0, 0, 0);
}

// round 6
// speedup vs baseline: 2.5202x; 1.4013x over previous
#include <cuda_runtime.h>
#include <cuda_bf16.h>
#include <math.h>
#include <stdint.h>

#define BATCH 8
#define SEQ 1024
#define DM 1024
#define NH 16
#define DH 64
#define RANK 128
#define NC 64
#define NQK 32
#define NV 32
#define QVLD 2048

typedef __nv_bfloat16 bf16;

// ---------------- scratch (device globals) ----------------
__device__ bf16 g_xhi[BATCH * SEQ * DM], g_xlo[BATCH * SEQ * DM];
__device__ bf16 g_wohi[DM * DM], g_wolo[DM * DM];
__device__ bf16 g_wcathi[128 * DM], g_wcatlo[128 * DM];
__device__ float g_log[BATCH * SEQ * 128];
__device__ float g_part[64 * 128];
__device__ int   g_idx[BATCH * 3 * 8];
__device__ float g_val[BATCH * 3 * 8];
__device__ bf16 g_schi[BATCH * RANK * DM], g_sclo[BATCH * RANK * DM];     // scT per batch [R][D]
__device__ bf16 g_eThi[BATCH * QVLD * RANK], g_eTlo[BATCH * QVLD * RANK]; // [eqkT(1024); evT(1024)] x 128
__device__ bf16 g_hhi[BATCH * SEQ * RANK], g_hlo[BATCH * SEQ * RANK];
__device__ bf16 g_qvhi[BATCH * SEQ * QVLD], g_qvlo[BATCH * SEQ * QVLD];   // cols 0-1023 Q, 1024-2047 V
__device__ bf16 g_atthi[BATCH * SEQ * DM], g_attlo[BATCH * SEQ * DM];

// ---------------- helpers ----------------
__device__ __forceinline__ unsigned pk2(float a, float b) {
    bf16 ha = __float2bfloat16_rn(a), hb = __float2bfloat16_rn(b);
    return ((unsigned)*(unsigned short*)&hb << 16) | *(unsigned short*)&ha;
}
__device__ __forceinline__ void split2(float a, float b, unsigned& hi, unsigned& lo) {
    bf16 ha = __float2bfloat16_rn(a), hb = __float2bfloat16_rn(b);
    hi = ((unsigned)*(unsigned short*)&hb << 16) | *(unsigned short*)&ha;
    lo = pk2(a - __bfloat162float(ha), b - __bfloat162float(hb));
}
__device__ __forceinline__ void mma16816(float* c, const unsigned* a, const unsigned* b) {
    asm volatile(
        "mma.sync.aligned.m16n8k16.row.col.f32.bf16.bf16.f32 "
        "{%0,%1,%2,%3},{%4,%5,%6,%7},{%8,%9},{%0,%1,%2,%3};\n"
        : "+f"(c[0]), "+f"(c[1]), "+f"(c[2]), "+f"(c[3])
        : "r"(a[0]), "r"(a[1]), "r"(a[2]), "r"(a[3]), "r"(b[0]), "r"(b[1]));
}
__device__ __forceinline__ void cpa16(bf16* dst, const bf16* src) {
    unsigned d = (unsigned)__cvta_generic_to_shared(dst);
    asm volatile("cp.async.cg.shared.global [%0], [%1], 16;\n" :: "r"(d), "l"(src));
}

// ---------------- split fp32 -> bf16 hi/lo ----------------
__global__ void split_kernel(const float* __restrict__ src, bf16* __restrict__ hi,
                             bf16* __restrict__ lo, long n) {
    long i = ((long)blockIdx.x * 256 + threadIdx.x) * 4;
    if (i >= n) return;
    float4 v = *(const float4*)(src + i);
    unsigned h0, l0, h1, l1;
    split2(v.x, v.y, h0, l0);
    split2(v.z, v.w, h1, l1);
    *(uint2*)(hi + i) = make_uint2(h0, h1);
    *(uint2*)(lo + i) = make_uint2(l0, l1);
}

// ---- concat router weights [Wc;Wqk;Wv] -> [128][1024] split bf16 ----
__global__ void concat_split(const float* __restrict__ Wc, const float* __restrict__ Wqk,
                             const float* __restrict__ Wv, bf16* __restrict__ hi,
                             bf16* __restrict__ lo) {
    long e = ((long)blockIdx.x * 256 + threadIdx.x) * 4;   // over 128*1024
    int row = (int)(e >> 10), col = (int)(e & 1023);
    const float* src = (row < NC) ? Wc + (long)row * DM
                     : (row < NC + NQK) ? Wqk + (long)(row - NC) * DM
                     : Wv + (long)(row - NC - NQK) * DM;
    float4 v = *(const float4*)(src + col);
    unsigned h0, l0, h1, l1;
    split2(v.x, v.y, h0, l0);
    split2(v.z, v.w, h1, l1);
    *(uint2*)(hi + e) = make_uint2(h0, h1);
    *(uint2*)(lo + e) = make_uint2(l0, l1);
}

// ---- fused softmax * importance + deterministic partial reduce ----
// logits combined layout: [row][128] = [c(64) | qk(32) | v(32)]
__global__ void __launch_bounds__(256) router_post(const float* __restrict__ lg,
                                                   const float* __restrict__ imp,
                                                   float* __restrict__ part) {
    int blk = blockIdx.x, bb = blk >> 3, sg = blk & 7;
    int w = threadIdx.x >> 5, lane = threadIdx.x & 31;
    long rowbase = (long)bb * SEQ + sg * 128 + w * 16;
    float aC0 = 0.f, aC1 = 0.f, aQ = 0.f, aV = 0.f;
    for (int it = 0; it < 16; it++) {
        long row = rowbase + it;
        const float* p = lg + row * 128;
        float wi = imp[row];
        float c0 = p[lane], c1 = p[32 + lane];
        float q0 = p[64 + lane];
        float v0 = p[96 + lane];
        float m = fmaxf(c0, c1);
#pragma unroll
        for (int o = 16; o >= 1; o >>= 1) m = fmaxf(m, __shfl_xor_sync(~0u, m, o));
        float e0 = __expf(c0 - m), e1 = __expf(c1 - m);
        float s = e0 + e1;
#pragma unroll
        for (int o = 16; o >= 1; o >>= 1) s += __shfl_xor_sync(~0u, s, o);
        float f = wi / s;
        aC0 += e0 * f; aC1 += e1 * f;
        m = q0;
#pragma unroll
        for (int o = 16; o >= 1; o >>= 1) m = fmaxf(m, __shfl_xor_sync(~0u, m, o));
        e0 = __expf(q0 - m);
        s = e0;
#pragma unroll
        for (int o = 16; o >= 1; o >>= 1) s += __shfl_xor_sync(~0u, s, o);
        aQ += e0 * wi / s;
        m = v0;
#pragma unroll
        for (int o = 16; o >= 1; o >>= 1) m = fmaxf(m, __shfl_xor_sync(~0u, m, o));
        e0 = __expf(v0 - m);
        s = e0;
#pragma unroll
        for (int o = 16; o >= 1; o >>= 1) s += __shfl_xor_sync(~0u, s, o);
        aV += e0 * wi / s;
    }
    __shared__ float ps[8][128];
    ps[w][lane] = aC0; ps[w][32 + lane] = aC1;
    ps[w][64 + lane] = aQ; ps[w][96 + lane] = aV;
    __syncthreads();
    int t = threadIdx.x;
    if (t < 128) {
        float s = 0.f;
#pragma unroll
        for (int ww = 0; ww < 8; ww++) s += ps[ww][t];
        part[blk * 128 + t] = s;
    }
}

// ---- final reduce + top-k (deterministic, fixed order) ----
__global__ void router_final(const float* __restrict__ part, int* __restrict__ idxo,
                             float* __restrict__ valo) {
    int b = blockIdx.x, t = threadIdx.x;  // 128 threads
    __shared__ float acc[128];
    float s = 0.f;
#pragma unroll
    for (int sg = 0; sg < 8; sg++) s += part[(b * 8 + sg) * 128 + t];
    acc[t] = s;
    __syncthreads();
    if (t < 3) {
        const int off[3] = {0, 64, 96};
        const int nn[3] = {64, 32, 32};
        const int kk[3] = {8, 4, 6};
        float v[64];
        int n = nn[t], k = kk[t];
        for (int i = 0; i < n; i++) v[i] = acc[off[t] + i];
        float sum = 0.f;
        for (int j = 0; j < k; j++) {
            int best = 0;
            float bv = v[0];
            for (int i = 1; i < n; i++) if (v[i] > bv) { bv = v[i]; best = i; }
            idxo[(b * 3 + t) * 8 + j] = best;
            valo[(b * 3 + t) * 8 + j] = bv;
            sum += bv;
            v[best] = -1e30f;
        }
        float inv = 1.f / (sum + 1e-8f);
        for (int j = 0; j < k; j++) valo[(b * 3 + t) * 8 + j] *= inv;
    }
}

// ---- sparse mix + transpose + split ----
// table [Nn][P][Q] -> out per batch [Q][P] (row stride P), batch stride bstride
__global__ void __launch_bounds__(256) mix_T_split(const float* __restrict__ table,
                                                   const int* __restrict__ idx,
                                                   const float* __restrict__ val,
                                                   int k, int g, int P, int Q, long bstride,
                                                   bf16* __restrict__ outhi,
                                                   bf16* __restrict__ outlo) {
    __shared__ float tile[32][33];
    int b = blockIdx.z;
    int q0 = blockIdx.x * 32, p0 = blockIdx.y * 32;
    int tx = threadIdx.x, ty = threadIdx.y;
    const int* id = idx + (b * 3 + g) * 8;
    const float* vl = val + (b * 3 + g) * 8;
    float wj[8];
    int ij[8];
#pragma unroll
    for (int j = 0; j < 8; j++) { wj[j] = (j < k) ? vl[j] : 0.f; ij[j] = (j < k) ? id[j] : 0; }
#pragma unroll
    for (int ii = 0; ii < 4; ii++) {
        int p = p0 + ty + 8 * ii;
        float s = 0.f;
        for (int j = 0; j < k; j++)
            s += wj[j] * table[((long)ij[j] * P + p) * Q + q0 + tx];
        tile[ty + 8 * ii][tx] = s;
    }
    __syncthreads();
    bf16* oh = outhi + (long)b * bstride;
    bf16* ol = outlo + (long)b * bstride;
#pragma unroll
    for (int ii = 0; ii < 4; ii++) {
        int q = q0 + ty + 8 * ii, p = p0 + tx;
        float v = tile[tx][ty + 8 * ii];
        bf16 h = __float2bfloat16_rn(v);
        oh[(long)q * P + p] = h;
        ol[(long)q * P + p] = __float2bfloat16_rn(v - __bfloat162float(h));
    }
}

// ---------------- bf16x3 tensor-core GEMM: C = A @ B^T, cp.async pipelined ----
// A (hi,lo): [M][K]; B (hi,lo): [N][K]. Tile BMx128, BK=32, 2-stage pipeline.
template<int BM, bool SPLIT_OUT>
__global__ void __launch_bounds__(256) gemm_tc(
    const bf16* __restrict__ Ahi, const bf16* __restrict__ Alo,
    const bf16* __restrict__ Bhi, const bf16* __restrict__ Blo,
    float* __restrict__ C, bf16* __restrict__ Chi, bf16* __restrict__ Clo,
    int M, int N, int K, int ldc, long sA, long sB, long sC)
{
    constexpr int MI = BM / 32;                 // m16 tiles per warp
    constexpr int ASZ = BM * 40;
    constexpr int BSZ = 128 * 40;
    constexpr int STAGE = 2 * ASZ + 2 * BSZ;
    extern __shared__ bf16 dyn[];

    const int tid = threadIdx.x, lane = tid & 31, w = tid >> 5;
    const int g = lane >> 2, t = lane & 3;
    const int wm = (w >> 2) * (16 * MI), wn = (w & 3) * 32;
    const int m0 = blockIdx.y * BM, n0 = blockIdx.x * 128;
    Ahi += (long)blockIdx.z * sA; Alo += (long)blockIdx.z * sA;
    Bhi += (long)blockIdx.z * sB; Blo += (long)blockIdx.z * sB;
    if (C)   C   += (long)blockIdx.z * sC;
    if (Chi) Chi += (long)blockIdx.z * sC;
    if (Clo) Clo += (long)blockIdx.z * sC;

    auto load_stage = [&](int st, int k0) {
        bf16* base = dyn + st * STAGE;
        bf16 *ash = base, *asl = base + ASZ, *bsh = base + 2 * ASZ, *bsl = base + 2 * ASZ + BSZ;
#pragma unroll
        for (int c = 0; c < BM / 64; c++) {
            int chunk = tid + 256 * c;
            int row = chunk >> 2, col = (chunk & 3) * 8;
            cpa16(&ash[row * 40 + col], Ahi + (long)(m0 + row) * K + k0 + col);
            cpa16(&asl[row * 40 + col], Alo + (long)(m0 + row) * K + k0 + col);
        }
#pragma unroll
        for (int c = 0; c < 2; c++) {
            int chunk = tid + 256 * c;
            int row = chunk >> 2, col = (chunk & 3) * 8;
            cpa16(&bsh[row * 40 + col], Bhi + (long)(n0 + row) * K + k0 + col);
            cpa16(&bsl[row * 40 + col], Blo + (long)(n0 + row) * K + k0 + col);
        }
    };

    float acc[MI][4][4] = {};
    const int NK = K >> 5;
    load_stage(0, 0);
    asm volatile("cp.async.commit_group;\n");

    for (int it = 0; it < NK; it++) {
        if (it + 1 < NK) {
            load_stage((it + 1) & 1, (it + 1) * 32);
            asm volatile("cp.async.commit_group;\n");
            asm volatile("cp.async.wait_group 1;\n");
        } else {
            asm volatile("cp.async.wait_group 0;\n");
        }
        __syncthreads();
        bf16* base = dyn + (it & 1) * STAGE;
        bf16 *Ash = base, *Asl = base + ASZ, *Bsh = base + 2 * ASZ, *Bsl = base + 2 * ASZ + BSZ;
#pragma unroll
        for (int ks = 0; ks < 2; ks++) {
            const int kk = ks * 16;
            unsigned ah[MI][4], al[MI][4], bh[4][2], bl[4][2];
#pragma unroll
            for (int i = 0; i < MI; i++) {
                int r = wm + 16 * i + g;
                ah[i][0] = *(unsigned*)&Ash[r * 40 + kk + 2 * t];
                ah[i][1] = *(unsigned*)&Ash[(r + 8) * 40 + kk + 2 * t];
                ah[i][2] = *(unsigned*)&Ash[r * 40 + kk + 8 + 2 * t];
                ah[i][3] = *(unsigned*)&Ash[(r + 8) * 40 + kk + 8 + 2 * t];
                al[i][0] = *(unsigned*)&Asl[r * 40 + kk + 2 * t];
                al[i][1] = *(unsigned*)&Asl[(r + 8) * 40 + kk + 2 * t];
                al[i][2] = *(unsigned*)&Asl[r * 40 + kk + 8 + 2 * t];
                al[i][3] = *(unsigned*)&Asl[(r + 8) * 40 + kk + 8 + 2 * t];
            }
#pragma unroll
            for (int j = 0; j < 4; j++) {
                int n = wn + 8 * j + g;
                bh[j][0] = *(unsigned*)&Bsh[n * 40 + kk + 2 * t];
                bh[j][1] = *(unsigned*)&Bsh[n * 40 + kk + 8 + 2 * t];
                bl[j][0] = *(unsigned*)&Bsl[n * 40 + kk + 2 * t];
                bl[j][1] = *(unsigned*)&Bsl[n * 40 + kk + 8 + 2 * t];
            }
#pragma unroll
            for (int i = 0; i < MI; i++)
#pragma unroll
                for (int j = 0; j < 4; j++) {
                    mma16816(acc[i][j], ah[i], bh[j]);
                    mma16816(acc[i][j], ah[i], bl[j]);
                    mma16816(acc[i][j], al[i], bh[j]);
                }
        }
        __syncthreads();
    }
#pragma unroll
    for (int i = 0; i < MI; i++) {
        int r = m0 + wm + 16 * i + g;
#pragma unroll
        for (int j = 0; j < 4; j++) {
            int cidx = n0 + wn + 8 * j + 2 * t;
            if (SPLIT_OUT) {
                unsigned hi, lo;
                split2(acc[i][j][0], acc[i][j][1], hi, lo);
                *(unsigned*)&Chi[(long)r * ldc + cidx] = hi;
                *(unsigned*)&Clo[(long)r * ldc + cidx] = lo;
                split2(acc[i][j][2], acc[i][j][3], hi, lo);
                *(unsigned*)&Chi[(long)(r + 8) * ldc + cidx] = hi;
                *(unsigned*)&Clo[(long)(r + 8) * ldc + cidx] = lo;
            } else {
                *(float2*)&C[(long)r * ldc + cidx] = make_float2(acc[i][j][0], acc[i][j][1]);
                *(float2*)&C[(long)(r + 8) * ldc + cidx] = make_float2(acc[i][j][2], acc[i][j][3]);
            }
        }
    }
}

// ---------------- tensor-core flash attention (K == Q), bf16x3 ----------------
// Q/V live in combined buffer with row stride QVLD; V at col offset +1024.
__global__ void __launch_bounds__(128) attn_tc(const bf16* __restrict__ Qh_g,
                                               const bf16* __restrict__ Ql_g,
                                               const bf16* __restrict__ Vh_g,
                                               const bf16* __restrict__ Vl_g,
                                               bf16* __restrict__ Ohi,
                                               bf16* __restrict__ Olo) {
    extern __shared__ bf16 sm[];
    bf16* Qs_h = sm;
    bf16* Qs_l = Qs_h + 64 * 72;
    bf16* Ks_h = Qs_l + 64 * 72;
    bf16* Ks_l = Ks_h + 64 * 72;
    bf16* Vs_h = Ks_l + 64 * 72;
    bf16* Vs_l = Vs_h + 64 * 72;

    const int qt = blockIdx.x, h = blockIdx.y, b = blockIdx.z;
    const int tid = threadIdx.x, lane = tid & 31, w = tid >> 5;
    const int g = lane >> 2, t = lane & 3;
    const long ho = (long)h * DH;
    const long bq = (long)b * SEQ + qt * 64;

#pragma unroll
    for (int c = 0; c < 4; c++) {
        int chunk = tid + 128 * c;
        int row = chunk >> 3, col = (chunk & 7) * 8;
        *(uint4*)&Qs_h[row * 72 + col] = *(const uint4*)(Qh_g + (bq + row) * QVLD + ho + col);
        *(uint4*)&Qs_l[row * 72 + col] = *(const uint4*)(Ql_g + (bq + row) * QVLD + ho + col);
    }

    float o[8][4] = {};
    float m0 = -1e30f, m1 = -1e30f, l0 = 0.f, l1 = 0.f;

    for (int kt = 0; kt <= qt; kt++) {
        const long bk = (long)b * SEQ + kt * 64;
#pragma unroll
        for (int c = 0; c < 4; c++) {
            int chunk = tid + 128 * c;
            int row = chunk >> 3, col = (chunk & 7) * 8;
            *(uint4*)&Ks_h[row * 72 + col] = *(const uint4*)(Qh_g + (bk + row) * QVLD + ho + col);
            *(uint4*)&Ks_l[row * 72 + col] = *(const uint4*)(Ql_g + (bk + row) * QVLD + ho + col);
            *(uint4*)&Vs_h[row * 72 + col] = *(const uint4*)(Vh_g + (bk + row) * QVLD + ho + col);
            *(uint4*)&Vs_l[row * 72 + col] = *(const uint4*)(Vl_g + (bk + row) * QVLD + ho + col);
        }
        __syncthreads();

        float s[8][4] = {};
#pragma unroll
        for (int kk = 0; kk < 4; kk++) {
            const int k16 = kk * 16;
            unsigned qa_h[4], qa_l[4];
            const int r = w * 16 + g;
            qa_h[0] = *(unsigned*)&Qs_h[r * 72 + k16 + 2 * t];
            qa_h[1] = *(unsigned*)&Qs_h[(r + 8) * 72 + k16 + 2 * t];
            qa_h[2] = *(unsigned*)&Qs_h[r * 72 + k16 + 8 + 2 * t];
            qa_h[3] = *(unsigned*)&Qs_h[(r + 8) * 72 + k16 + 8 + 2 * t];
            qa_l[0] = *(unsigned*)&Qs_l[r * 72 + k16 + 2 * t];
            qa_l[1] = *(unsigned*)&Qs_l[(r + 8) * 72 + k16 + 2 * t];
            qa_l[2] = *(unsigned*)&Qs_l[r * 72 + k16 + 8 + 2 * t];
            qa_l[3] = *(unsigned*)&Qs_l[(r + 8) * 72 + k16 + 8 + 2 * t];
#pragma unroll
            for (int j = 0; j < 8; j++) {
                const int n = 8 * j + g;
                unsigned kb_h[2], kb_l[2];
                kb_h[0] = *(unsigned*)&Ks_h[n * 72 + k16 + 2 * t];
                kb_h[1] = *(unsigned*)&Ks_h[n * 72 + k16 + 8 + 2 * t];
                kb_l[0] = *(unsigned*)&Ks_l[n * 72 + k16 + 2 * t];
                kb_l[1] = *(unsigned*)&Ks_l[n * 72 + k16 + 8 + 2 * t];
                mma16816(s[j], qa_h, kb_h);
                mma16816(s[j], qa_h, kb_l);
                mma16816(s[j], qa_l, kb_h);
            }
        }
        const bool diag = (kt == qt);
        const int lim0 = w * 16 + g, lim1 = lim0 + 8;
#pragma unroll
        for (int j = 0; j < 8; j++) {
#pragma unroll
            for (int e = 0; e < 4; e++) s[j][e] *= 0.125f;
            if (diag) {
                int col = 8 * j + 2 * t;
                if (col > lim0) s[j][0] = -1e30f;
                if (col + 1 > lim0) s[j][1] = -1e30f;
                if (col > lim1) s[j][2] = -1e30f;
                if (col + 1 > lim1) s[j][3] = -1e30f;
            }
        }
        float mx0 = -1e30f, mx1 = -1e30f;
#pragma unroll
        for (int j = 0; j < 8; j++) {
            mx0 = fmaxf(mx0, fmaxf(s[j][0], s[j][1]));
            mx1 = fmaxf(mx1, fmaxf(s[j][2], s[j][3]));
        }
        mx0 = fmaxf(mx0, __shfl_xor_sync(~0u, mx0, 1));
        mx0 = fmaxf(mx0, __shfl_xor_sync(~0u, mx0, 2));
        mx1 = fmaxf(mx1, __shfl_xor_sync(~0u, mx1, 1));
        mx1 = fmaxf(mx1, __shfl_xor_sync(~0u, mx1, 2));
        float mn0 = fmaxf(m0, mx0), mn1 = fmaxf(m1, mx1);
        float al0 = __expf(m0 - mn0), al1 = __expf(m1 - mn1);
        m0 = mn0; m1 = mn1;
        float sum0 = 0.f, sum1 = 0.f;
#pragma unroll
        for (int j = 0; j < 8; j++) {
            s[j][0] = __expf(s[j][0] - mn0); sum0 += s[j][0];
            s[j][1] = __expf(s[j][1] - mn0); sum0 += s[j][1];
            s[j][2] = __expf(s[j][2] - mn1); sum1 += s[j][2];
            s[j][3] = __expf(s[j][3] - mn1); sum1 += s[j][3];
        }
        sum0 += __shfl_xor_sync(~0u, sum0, 1);
        sum0 += __shfl_xor_sync(~0u, sum0, 2);
        sum1 += __shfl_xor_sync(~0u, sum1, 1);
        sum1 += __shfl_xor_sync(~0u, sum1, 2);
        l0 = l0 * al0 + sum0;
        l1 = l1 * al1 + sum1;
#pragma unroll
        for (int j = 0; j < 8; j++) {
            o[j][0] *= al0; o[j][1] *= al0;
            o[j][2] *= al1; o[j][3] *= al1;
        }
#pragma unroll
        for (int kk = 0; kk < 4; kk++) {
            unsigned pa_h[4], pa_l[4];
            split2(s[2 * kk][0], s[2 * kk][1], pa_h[0], pa_l[0]);
            split2(s[2 * kk][2], s[2 * kk][3], pa_h[1], pa_l[1]);
            split2(s[2 * kk + 1][0], s[2 * kk + 1][1], pa_h[2], pa_l[2]);
            split2(s[2 * kk + 1][2], s[2 * kk + 1][3], pa_h[3], pa_l[3]);
            const int kb = 16 * kk + 2 * t;
#pragma unroll
            for (int j = 0; j < 8; j++) {
                const int n = 8 * j + g;
                unsigned vb_h[2], vb_l[2];
                unsigned short x0, x1;
                x0 = *(const unsigned short*)&Vs_h[kb * 72 + n];
                x1 = *(const unsigned short*)&Vs_h[(kb + 1) * 72 + n];
                vb_h[0] = x0 | ((unsigned)x1 << 16);
                x0 = *(const unsigned short*)&Vs_h[(kb + 8) * 72 + n];
                x1 = *(const unsigned short*)&Vs_h[(kb + 9) * 72 + n];
                vb_h[1] = x0 | ((unsigned)x1 << 16);
                x0 = *(const unsigned short*)&Vs_l[kb * 72 + n];
                x1 = *(const unsigned short*)&Vs_l[(kb + 1) * 72 + n];
                vb_l[0] = x0 | ((unsigned)x1 << 16);
                x0 = *(const unsigned short*)&Vs_l[(kb + 8) * 72 + n];
                x1 = *(const unsigned short*)&Vs_l[(kb + 9) * 72 + n];
                vb_l[1] = x0 | ((unsigned)x1 << 16);
                mma16816(o[j], pa_h, vb_h);
                mma16816(o[j], pa_h, vb_l);
                mma16816(o[j], pa_l, vb_h);
            }
        }
        __syncthreads();
    }
    const float il0 = 1.f / l0, il1 = 1.f / l1;
    const long row0 = bq + w * 16 + g, row1 = row0 + 8;
#pragma unroll
    for (int j = 0; j < 8; j++) {
        const long col = ho + 8 * j + 2 * t;
        unsigned hi, lo;
        split2(o[j][0] * il0, o[j][1] * il0, hi, lo);
        *(unsigned*)&Ohi[row0 * DM + col] = hi;
        *(unsigned*)&Olo[row0 * DM + col] = lo;
        split2(o[j][2] * il1, o[j][3] * il1, hi, lo);
        *(unsigned*)&Ohi[row1 * DM + col] = hi;
        *(unsigned*)&Olo[row1 * DM + col] = lo;
    }
}

// ---------------- host ----------------
extern "C" void kernel_launch(void* const* d_in, const int* in_sizes, int n_in,
                              void* d_out, int out_size) {
    const float* x   = (const float*)d_in[0];
    const float* imp = (const float*)d_in[1];
    const float* Wc  = (const float*)d_in[2];
    const float* Wqk = (const float*)d_in[3];
    const float* Wv  = (const float*)d_in[4];
    const float* cn  = (const float*)d_in[5];
    const float* eQK = (const float*)d_in[6];
    const float* eV  = (const float*)d_in[7];
    const float* Wo  = (const float*)d_in[8];
    float* out = (float*)d_out;

    bf16 *xhi, *xlo, *wohi, *wolo, *wcathi, *wcatlo, *schi, *sclo, *eThi, *eTlo;
    bf16 *hhi, *hlo, *qvhi, *qvlo, *atthi, *attlo;
    float *lg, *part, *val;
    int* idx;
    cudaGetSymbolAddress((void**)&xhi, g_xhi);       cudaGetSymbolAddress((void**)&xlo, g_xlo);
    cudaGetSymbolAddress((void**)&wohi, g_wohi);     cudaGetSymbolAddress((void**)&wolo, g_wolo);
    cudaGetSymbolAddress((void**)&wcathi, g_wcathi); cudaGetSymbolAddress((void**)&wcatlo, g_wcatlo);
    cudaGetSymbolAddress((void**)&lg, g_log);        cudaGetSymbolAddress((void**)&part, g_part);
    cudaGetSymbolAddress((void**)&idx, g_idx);       cudaGetSymbolAddress((void**)&val, g_val);
    cudaGetSymbolAddress((void**)&schi, g_schi);     cudaGetSymbolAddress((void**)&sclo, g_sclo);
    cudaGetSymbolAddress((void**)&eThi, g_eThi);     cudaGetSymbolAddress((void**)&eTlo, g_eTlo);
    cudaGetSymbolAddress((void**)&hhi, g_hhi);       cudaGetSymbolAddress((void**)&hlo, g_hlo);
    cudaGetSymbolAddress((void**)&qvhi, g_qvhi);     cudaGetSymbolAddress((void**)&qvlo, g_qvlo);
    cudaGetSymbolAddress((void**)&atthi, g_atthi);   cudaGetSymbolAddress((void**)&attlo, g_attlo);

    // capture-safe attribute setup (no static guards; not a stream op)
    cudaFuncSetAttribute(gemm_tc<64, false>,  cudaFuncAttributeMaxDynamicSharedMemorySize, 61440);
    cudaFuncSetAttribute(gemm_tc<64, true>,   cudaFuncAttributeMaxDynamicSharedMemorySize, 61440);
    cudaFuncSetAttribute(gemm_tc<128, true>,  cudaFuncAttributeMaxDynamicSharedMemorySize, 81920);
    cudaFuncSetAttribute(gemm_tc<128, false>, cudaFuncAttributeMaxDynamicSharedMemorySize, 81920);
    cudaFuncSetAttribute(attn_tc, cudaFuncAttributeMaxDynamicSharedMemorySize, 55296);

    // splits + router weight concat
    split_kernel<<<8192, 256>>>(x, xhi, xlo, (long)BATCH * SEQ * DM);
    split_kernel<<<1024, 256>>>(Wo, wohi, wolo, (long)DM * DM);
    concat_split<<<128, 256>>>(Wc, Wqk, Wv, wcathi, wcatlo);

    // router logits via tensor cores: [8192,128] = x @ Wcat^T
    gemm_tc<64, false><<<dim3(1, 128, 1), 256, 61440>>>(xhi, xlo, wcathi, wcatlo,
        lg, nullptr, nullptr, BATCH * SEQ, 128, DM, 128, 0, 0, 0);
    router_post<<<64, 256>>>(lg, imp, part);
    router_final<<<BATCH, 128>>>(part, idx, val);

    // sparse mixes (transposed + split)
    mix_T_split<<<dim3(RANK / 32, DM / 32, BATCH), dim3(32, 8)>>>(
        cn, idx, val, 8, 0, DM, RANK, (long)RANK * DM, schi, sclo);
    mix_T_split<<<dim3(DM / 32, RANK / 32, BATCH), dim3(32, 8)>>>(
        eQK, idx, val, 4, 1, RANK, DM, (long)QVLD * RANK, eThi, eTlo);
    mix_T_split<<<dim3(DM / 32, RANK / 32, BATCH), dim3(32, 8)>>>(
        eV, idx, val, 6, 2, RANK, DM, (long)QVLD * RANK,
        eThi + (long)DM * RANK, eTlo + (long)DM * RANK);

    // h = x @ scT^T  [1024x128], K=1024 (BM=64 -> 128 CTAs)
    gemm_tc<64, true><<<dim3(1, 16, BATCH), 256, 61440>>>(xhi, xlo, schi, sclo,
        nullptr, hhi, hlo, SEQ, RANK, DM, RANK,
        (long)SEQ * DM, (long)RANK * DM, (long)SEQ * RANK);

    // QV = h @ [eqkT; evT]^T  [1024 x 2048], K=128 (1024 CTAs)
    gemm_tc<128, true><<<dim3(QVLD / 128, SEQ / 128, BATCH), 256, 81920>>>(hhi, hlo, eThi, eTlo,
        nullptr, qvhi, qvlo, SEQ, QVLD, RANK, QVLD,
        (long)SEQ * RANK, (long)QVLD * RANK, (long)SEQ * QVLD);

    // attention (Q cols 0-1023, V cols 1024-2047 of qv buffer)
    attn_tc<<<dim3(SEQ / 64, NH, BATCH), 128, 55296>>>(
        qvhi, qvlo, qvhi + 1024, qvlo + 1024, atthi, attlo);

    // out = att @ Wo^T  [8192x1024], K=1024, fp32 out
    gemm_tc<128, false><<<dim3(8, 64, 1), 256, 81920>>>(atthi, attlo, wohi, wolo,
        out, nullptr, nullptr, BATCH * SEQ, DM, DM, DM, 0, 0, 0);
}